// round 3
// baseline (speedup 1.0000x reference)
#include <cuda_runtime.h>
#include <math.h>

#define THREADS 512
#define CE_BLOCKS 128
#define EDGE_BLOCKS 464
#define NWARPS (THREADS / 32)

__global__ void hx_init_out(float* out) {
    if (threadIdx.x == 0 && blockIdx.x == 0) out[0] = 0.0f;
}

__global__ __launch_bounds__(THREADS) void hierarchy_loss_fused(
    const float* __restrict__ logits,
    const int*   __restrict__ labels,
    const float* __restrict__ emb,
    const int*   __restrict__ parent_idx,
    const int*   __restrict__ child_idx,
    int N, int D, int E, int B,
    float* __restrict__ out)
{
    __shared__ float red[NWARPS];
    const int tid  = threadIdx.x;
    const int lane = tid & 31;
    const int warp = tid >> 5;

    if (blockIdx.x < CE_BLOCKS) {
        // ---------------- Cross-entropy: one row per block ----------------
        const int row = blockIdx.x;
        const float* rowp = logits + (size_t)row * N;
        const float4* rowp4 = (const float4*)rowp;
        const int n4 = N >> 2;

        // Pass 1: row max (streams from DRAM)
        float m = -INFINITY;
        for (int i = tid; i < n4; i += THREADS) {
            float4 v = rowp4[i];
            m = fmaxf(m, fmaxf(fmaxf(v.x, v.y), fmaxf(v.z, v.w)));
        }
        for (int i = (n4 << 2) + tid; i < N; i += THREADS)
            m = fmaxf(m, rowp[i]);
        #pragma unroll
        for (int o = 16; o; o >>= 1) m = fmaxf(m, __shfl_xor_sync(0xffffffffu, m, o));
        if (lane == 0) red[warp] = m;
        __syncthreads();
        if (warp == 0) {
            float t = (lane < NWARPS) ? red[lane] : -INFINITY;
            #pragma unroll
            for (int o = 16; o; o >>= 1) t = fmaxf(t, __shfl_xor_sync(0xffffffffu, t, o));
            if (lane == 0) red[0] = t;
        }
        __syncthreads();
        m = red[0];
        __syncthreads();

        // Pass 2: sum of exp (re-read hits L2)
        float s = 0.0f;
        for (int i = tid; i < n4; i += THREADS) {
            float4 v = rowp4[i];
            s += __expf(v.x - m) + __expf(v.y - m) + __expf(v.z - m) + __expf(v.w - m);
        }
        for (int i = (n4 << 2) + tid; i < N; i += THREADS)
            s += __expf(rowp[i] - m);
        #pragma unroll
        for (int o = 16; o; o >>= 1) s += __shfl_xor_sync(0xffffffffu, s, o);
        if (lane == 0) red[warp] = s;
        __syncthreads();
        if (tid == 0) {
            float total = 0.0f;
            #pragma unroll
            for (int w = 0; w < NWARPS; w++) total += red[w];
            int lab = labels[row];
            float x = rowp[lab];
            float ce = -(x - m - __logf(total));
            atomicAdd(out, ce / (float)B);
        }
    } else {
        // ---------------- Hierarchy penalty: one warp per edge ----------------
        const int nEdgeBlocks = (int)gridDim.x - CE_BLOCKS;
        const int gwarp = (blockIdx.x - CE_BLOCKS) * NWARPS + warp;
        const int totalWarps = nEdgeBlocks * NWARPS;
        const int d4 = D >> 2;  // float4 per row (64 for D=256)

        float acc = 0.0f;
        for (int e = gwarp; e < E; e += totalWarps) {
            const int p = parent_idx[e];
            const int c = child_idx[e];
            const float4* pr = (const float4*)(emb + (size_t)p * D);
            const float4* cr = (const float4*)(emb + (size_t)c * D);
            for (int j = lane; j < d4; j += 32) {
                float4 a = pr[j];
                float4 b = cr[j];
                float dx = a.x - b.x;
                float dy = a.y - b.y;
                float dz = a.z - b.z;
                float dw = a.w - b.w;
                acc += dx * dx + dy * dy + dz * dz + dw * dw;
            }
        }
        #pragma unroll
        for (int o = 16; o; o >>= 1) acc += __shfl_xor_sync(0xffffffffu, acc, o);
        if (lane == 0) red[warp] = acc;
        __syncthreads();
        if (tid == 0) {
            float t = 0.0f;
            #pragma unroll
            for (int w = 0; w < NWARPS; w++) t += red[w];
            atomicAdd(out, 0.1f * t);
        }
    }
}

extern "C" void kernel_launch(void* const* d_in, const int* in_sizes, int n_in,
                              void* d_out, int out_size) {
    const float* logits = (const float*)d_in[0];
    const int*   labels = (const int*)d_in[1];
    const float* emb    = (const float*)d_in[2];
    const int*   par    = (const int*)d_in[3];
    const int*   chi    = (const int*)d_in[4];
    float* out = (float*)d_out;

    const int B = in_sizes[1];            // 128
    const int N = in_sizes[0] / B;        // 100000
    const int D = in_sizes[2] / N;        // 256
    const int E = in_sizes[3];            // 99999

    hx_init_out<<<1, 32>>>(out);
    hierarchy_loss_fused<<<CE_BLOCKS + EDGE_BLOCKS, THREADS>>>(
        logits, labels, emb, par, chi, N, D, E, B, out);
}